// round 1
// baseline (speedup 1.0000x reference)
#include <cuda_runtime.h>

#define NN   2048
#define CDIM 256      // K*D
#define KCH  8
#define TN   32       // n-tile
#define TMT  32       // m-tile
#define MS   4        // m splits across grid.y
#define ZS   260      // padded smem row stride (floats) to kill bank conflicts

__device__ float    g_Z[2][NN * CDIM];       // ping-pong Z, [n][k*32+d]
__device__ float    g_part[MS][NN * CDIM];   // per-m-split partial aggregates
__device__ unsigned g_maskbits[NN * (NN / 32)];

// ---------------- pack adjacency to bitmask ----------------
__global__ void pack_mask_kernel(const int* __restrict__ adj) {
    int w = blockIdx.x * 256 + threadIdx.x;          // word index: n = w>>6, mword = w&63
    const int4* p = ((const int4*)adj) + (size_t)w * 8;
    unsigned bits = 0;
#pragma unroll
    for (int j = 0; j < 8; j++) {
        int4 v = p[j];
        if (v.x > 0) bits |= 1u << (4 * j + 0);
        if (v.y > 0) bits |= 1u << (4 * j + 1);
        if (v.z > 0) bits |= 1u << (4 * j + 2);
        if (v.w > 0) bits |= 1u << (4 * j + 3);
    }
    g_maskbits[w] = bits;
}

// ---------------- projection + L2 norm -> g_Z[0] ----------------
__global__ void proj_kernel(const float* __restrict__ feat,
                            const float* __restrict__ W,
                            const float* __restrict__ b) {
    __shared__ float fs[128];
    int n = blockIdx.x, t = threadIdx.x;
    if (t < 128) fs[t] = feat[n * 128 + t];
    __syncthreads();
    int k = t >> 5, d = t & 31;
    const float* Wp = W + k * 4096 + d;              // W[k][i][d], stride 32 over i
    float s = b[t];                                  // b[k*32+d]
#pragma unroll 16
    for (int i = 0; i < 128; i++) s = fmaf(fs[i], Wp[i * 32], s);
    float ss = s * s;
#pragma unroll
    for (int o = 16; o; o >>= 1) ss += __shfl_xor_sync(0xffffffffu, ss, o);
    float inv = 1.0f / fmaxf(sqrtf(ss), 1e-12f);
    g_Z[0][(size_t)n * CDIM + t] = s * inv;
}

// ---------------- fused scores + channel-softmax + aggregation ----------------
// grid: (NN/TN, MS), 256 threads. Each block: TN rows x (NN/MS) columns.
__global__ __launch_bounds__(256, 2) void iter_kernel(int zi) {
    extern __shared__ char smem_raw[];
    float (*Zn_s)[ZS]       = (float(*)[ZS])(smem_raw);
    float (*Zm_s)[ZS]       = (float(*)[ZS])(smem_raw + TN * ZS * 4);
    float (*att_s)[TN][TMT] = (float(*)[TN][TMT])(smem_raw + 2 * TN * ZS * 4);

    const float* __restrict__ Z = g_Z[zi];
    int t  = threadIdx.x;
    int n0 = blockIdx.x * TN;
    int mbase = blockIdx.y * (NN / MS);

    // load Zn tile (TN x 256)
    {
        const float4* src = (const float4*)(Z + (size_t)n0 * CDIM);
#pragma unroll
        for (int j = 0; j < 8; j++) {
            int idx = t + j * 256;
            int row = idx >> 6, col = idx & 63;
            *(float4*)&Zn_s[row][col * 4] = src[idx];
        }
    }

    int ty = t >> 4, tx = t & 15;     // phase A mapping (2x2 micro-tile)
    int k  = t >> 5, d  = t & 31;     // phase B mapping (warp=channel, lane=dim)

    float acc[TN];
#pragma unroll
    for (int i = 0; i < TN; i++) acc[i] = 0.f;

    const int NTILES = (NN / MS) / TMT;
    for (int mt = 0; mt < NTILES; mt++) {
        int m0 = mbase + mt * TMT;
        __syncthreads();   // protect Zm_s from previous phase B
        {
            const float4* src = (const float4*)(Z + (size_t)m0 * CDIM);
#pragma unroll
            for (int j = 0; j < 8; j++) {
                int idx = t + j * 256;
                int row = idx >> 6, col = idx & 63;
                *(float4*)&Zm_s[row][col * 4] = src[idx];
            }
        }
        __syncthreads();

        // ---- Phase A: 8 per-channel dots for 4 (n,m) pairs + channel softmax ----
        float sk[8][4];
#pragma unroll
        for (int kk = 0; kk < 8; kk++) {
            float4 c00 = make_float4(0, 0, 0, 0), c01 = c00, c10 = c00, c11 = c00;
#pragma unroll
            for (int c = 0; c < 32; c += 4) {
                float4 a0 = *(const float4*)&Zn_s[ty][kk * 32 + c];
                float4 a1 = *(const float4*)&Zn_s[ty + 16][kk * 32 + c];
                float4 b0 = *(const float4*)&Zm_s[tx][kk * 32 + c];
                float4 b1 = *(const float4*)&Zm_s[tx + 16][kk * 32 + c];
                c00.x = fmaf(a0.x, b0.x, c00.x); c00.y = fmaf(a0.y, b0.y, c00.y);
                c00.z = fmaf(a0.z, b0.z, c00.z); c00.w = fmaf(a0.w, b0.w, c00.w);
                c01.x = fmaf(a0.x, b1.x, c01.x); c01.y = fmaf(a0.y, b1.y, c01.y);
                c01.z = fmaf(a0.z, b1.z, c01.z); c01.w = fmaf(a0.w, b1.w, c01.w);
                c10.x = fmaf(a1.x, b0.x, c10.x); c10.y = fmaf(a1.y, b0.y, c10.y);
                c10.z = fmaf(a1.z, b0.z, c10.z); c10.w = fmaf(a1.w, b0.w, c10.w);
                c11.x = fmaf(a1.x, b1.x, c11.x); c11.y = fmaf(a1.y, b1.y, c11.y);
                c11.z = fmaf(a1.z, b1.z, c11.z); c11.w = fmaf(a1.w, b1.w, c11.w);
            }
            sk[kk][0] = (c00.x + c00.y) + (c00.z + c00.w);
            sk[kk][1] = (c01.x + c01.y) + (c01.z + c01.w);
            sk[kk][2] = (c10.x + c10.y) + (c10.z + c10.w);
            sk[kk][3] = (c11.x + c11.y) + (c11.z + c11.w);
        }

        int mw = m0 >> 5;
        unsigned w0 = g_maskbits[(n0 + ty) * 64 + mw];
        unsigned w1 = g_maskbits[(n0 + ty + 16) * 64 + mw];
        unsigned bitsv[4] = { (w0 >> tx) & 1u, (w0 >> (tx + 16)) & 1u,
                              (w1 >> tx) & 1u, (w1 >> (tx + 16)) & 1u };
        int nyv[4] = { ty, ty, ty + 16, ty + 16 };
        int mxv[4] = { tx, tx + 16, tx, tx + 16 };
#pragma unroll
        for (int p = 0; p < 4; p++) {
            // |s| <= 1 (unit rows) -> softmax without max subtraction is safe
            float sum = 0.f;
#pragma unroll
            for (int kk = 0; kk < 8; kk++) { float e = __expf(sk[kk][p]); sk[kk][p] = e; sum += e; }
            float inv = bitsv[p] ? (1.0f / sum) : 0.0f;
#pragma unroll
            for (int kk = 0; kk < 8; kk++) att_s[kk][nyv[p]][mxv[p]] = sk[kk][p] * inv;
        }
        __syncthreads();

        // ---- Phase B: acc[k][n][d] += att[k][n][m] * Z[k][m][d] ----
#pragma unroll
        for (int mq = 0; mq < 8; mq++) {
            float z0 = Zm_s[mq * 4 + 0][k * 32 + d];
            float z1 = Zm_s[mq * 4 + 1][k * 32 + d];
            float z2 = Zm_s[mq * 4 + 2][k * 32 + d];
            float z3 = Zm_s[mq * 4 + 3][k * 32 + d];
#pragma unroll
            for (int ny = 0; ny < TN; ny++) {
                float4 a = *(const float4*)&att_s[k][ny][mq * 4];  // warp-broadcast
                acc[ny] = fmaf(a.x, z0, acc[ny]);
                acc[ny] = fmaf(a.y, z1, acc[ny]);
                acc[ny] = fmaf(a.z, z2, acc[ny]);
                acc[ny] = fmaf(a.w, z3, acc[ny]);
            }
        }
    }

    float* dst = g_part[blockIdx.y];
#pragma unroll
    for (int ny = 0; ny < TN; ny++)
        dst[(size_t)(n0 + ny) * CDIM + k * 32 + d] = acc[ny];
}

// ---------------- residual + sum partials + L2 norm ----------------
__global__ void norm_kernel(int zi, int zo, float* __restrict__ outp) {
    int n = blockIdx.x, t = threadIdx.x;
    size_t i = (size_t)n * CDIM + t;
    float v = g_Z[zi][i] + g_part[0][i] + g_part[1][i] + g_part[2][i] + g_part[3][i];
    float ss = v * v;
#pragma unroll
    for (int o = 16; o; o >>= 1) ss += __shfl_xor_sync(0xffffffffu, ss, o);
    float r = v / fmaxf(sqrtf(ss), 1e-12f);
    if (outp) outp[i] = r; else g_Z[zo][i] = r;
}

extern "C" void kernel_launch(void* const* d_in, const int* in_sizes, int n_in,
                              void* d_out, int out_size) {
    const int* adj = nullptr; const float* feat = nullptr;
    const float* W = nullptr; const float* b = nullptr;
    for (int i = 0; i < n_in; i++) {
        switch (in_sizes[i]) {
            case NN * NN:     adj  = (const int*)d_in[i];   break;
            case NN * 128:    feat = (const float*)d_in[i]; break;
            case 8 * 128 * 32: W   = (const float*)d_in[i]; break;
            case 256:         b    = (const float*)d_in[i]; break;
        }
    }
    float* out = (float*)d_out;

    const int SMEM = (2 * TN * ZS + KCH * TN * TMT) * 4;   // 99328 bytes
    cudaFuncSetAttribute(iter_kernel, cudaFuncAttributeMaxDynamicSharedMemorySize, SMEM);

    pack_mask_kernel<<<NN * (NN / 32) / 256, 256>>>(adj);
    proj_kernel<<<NN, 256>>>(feat, W, b);

    int cur = 0;
    for (int it = 0; it < 4; it++) {
        dim3 grid(NN / TN, MS);
        iter_kernel<<<grid, 256, SMEM>>>(cur);
        norm_kernel<<<NN, 256>>>(cur, cur ^ 1, (it == 3) ? out : nullptr);
        cur ^= 1;
    }
}

// round 2
// speedup vs baseline: 1.1720x; 1.1720x over previous
#include <cuda_runtime.h>

#define NN   2048
#define CDIM 256      // K*D
#define KCH  8
#define TN   32       // n-tile per block
#define TMT  32       // m-tile
#define MS   4        // m splits across grid.y
#define ZS   260      // padded smem row stride (floats)

typedef unsigned long long ull;

__device__ float    g_Z[2][NN * CDIM];       // ping-pong Z, [n][k*32+d]
__device__ float    g_part[MS][NN * CDIM];   // per-m-split partial aggregates
__device__ unsigned g_maskT[NN * (NN / 32)]; // transposed mask bits: word[m*64+nw], bit i = adj[nw*32+i][m]

// ---------- f32x2 helpers ----------
__device__ __forceinline__ void fma2(ull& d, ull a, ull b) {
    asm("fma.rn.f32x2 %0, %1, %2, %0;" : "+l"(d) : "l"(a), "l"(b));
}
__device__ __forceinline__ ull pk(float x, float y) {
    ull r; asm("mov.b64 %0, {%1, %2};" : "=l"(r) : "f"(x), "f"(y)); return r;
}
__device__ __forceinline__ ull bc2(float x) {
    ull r; asm("mov.b64 %0, {%1, %1};" : "=l"(r) : "f"(x)); return r;
}
__device__ __forceinline__ float2 up2(ull v) {
    float2 r; asm("mov.b64 {%0, %1}, %2;" : "=f"(r.x), "=f"(r.y) : "l"(v)); return r;
}

// ---------------- transposed mask pack ----------------
__global__ void pack_maskT_kernel(const int* __restrict__ adj) {
    int nw = blockIdx.x;                       // 0..63
    int m  = blockIdx.y * 256 + threadIdx.x;   // 0..2047
    unsigned bits = 0;
#pragma unroll 8
    for (int i = 0; i < 32; i++)
        bits |= (adj[(size_t)(nw * 32 + i) * NN + m] > 0 ? 1u : 0u) << i;
    g_maskT[m * 64 + nw] = bits;
}

// ---------------- projection + L2 norm -> g_Z[0] ----------------
__global__ void proj_kernel(const float* __restrict__ feat,
                            const float* __restrict__ W,
                            const float* __restrict__ b) {
    __shared__ float fs[128];
    int n = blockIdx.x, t = threadIdx.x;
    if (t < 128) fs[t] = feat[n * 128 + t];
    __syncthreads();
    int k = t >> 5, d = t & 31;
    const float* Wp = W + k * 4096 + d;
    float s = b[t];
#pragma unroll 16
    for (int i = 0; i < 128; i++) s = fmaf(fs[i], Wp[i * 32], s);
    float ss = s * s;
#pragma unroll
    for (int o = 16; o; o >>= 1) ss += __shfl_xor_sync(0xffffffffu, ss, o);
    float inv = 1.0f / fmaxf(sqrtf(ss), 1e-12f);
    g_Z[0][(size_t)n * CDIM + t] = s * inv;
}

// ---------------- fused scores + channel-softmax + aggregation ----------------
// grid (NN/TN, MS), 256 threads, 2 blocks/SM.
__global__ __launch_bounds__(256, 2) void iter_kernel(int zi) {
    extern __shared__ char smem_raw[];
    float (*Zn_s)[ZS]        = (float(*)[ZS])(smem_raw);
    float (*Zm_s)[ZS]        = (float(*)[ZS])(smem_raw + TN * ZS * 4);
    float (*att_s)[TMT][TN]  = (float(*)[TMT][TN])(smem_raw + 2 * TN * ZS * 4); // [k][m][n]

    const float* __restrict__ Z = g_Z[zi];
    int t     = threadIdx.x;
    int n0    = blockIdx.x * TN;
    int mbase = blockIdx.y * (NN / MS);

    // load Zn tile (TN x 256)
    {
        const float4* src = (const float4*)(Z + (size_t)n0 * CDIM);
#pragma unroll
        for (int j = 0; j < 8; j++) {
            int idx = t + j * 256;
            *(float4*)&Zn_s[idx >> 6][(idx & 63) * 4] = src[idx];
        }
    }

    // Phase A mapping: 4 channel-groups of 64 threads; 8x8 thread grid; 4x4 pair tile
    int ch0 = t >> 6;            // 0..3 (channels ch0 and ch0+4)
    int tyy = (t & 63) >> 3;     // 0..7 -> m rows {tyy+8i}
    int txx = t & 7;             // 0..7 -> n cols {txx+8j}
    // Phase B mapping: warp = channel, lane = dim
    int kb = t >> 5, d = t & 31;

    ull acc2[16];                // 32 n-values packed in pairs, fixed (kb, d)
#pragma unroll
    for (int q = 0; q < 16; q++) acc2[q] = 0ull;

    const int NTILES = (NN / MS) / TMT;
    for (int mt = 0; mt < NTILES; mt++) {
        int m0 = mbase + mt * TMT;
        __syncthreads();
        {
            const float4* src = (const float4*)(Z + (size_t)m0 * CDIM);
#pragma unroll
            for (int j = 0; j < 8; j++) {
                int idx = t + j * 256;
                *(float4*)&Zm_s[idx >> 6][(idx & 63) * 4] = src[idx];
            }
        }
        __syncthreads();

        // ---- Phase A: raw scores -> att_s[ch][m][n] (f32x2 GEMM-let, 4x4/thread) ----
#pragma unroll
        for (int cc = 0; cc < 2; cc++) {
            int ch = ch0 + cc * 4;
            ull sacc[16];
#pragma unroll
            for (int q = 0; q < 16; q++) sacc[q] = 0ull;
#pragma unroll
            for (int s2 = 0; s2 < 8; s2++) {     // 4 dims per step
                ull a0[4], a1[4], b0[4], b1[4];
#pragma unroll
                for (int j = 0; j < 4; j++) {
                    float4 v = *(const float4*)&Zn_s[txx + 8 * j][ch * 32 + 4 * s2];
                    a0[j] = pk(v.x, v.y); a1[j] = pk(v.z, v.w);
                }
#pragma unroll
                for (int i = 0; i < 4; i++) {
                    float4 v = *(const float4*)&Zm_s[tyy + 8 * i][ch * 32 + 4 * s2];
                    b0[i] = pk(v.x, v.y); b1[i] = pk(v.z, v.w);
                }
#pragma unroll
                for (int i = 0; i < 4; i++)
#pragma unroll
                    for (int j = 0; j < 4; j++) {
                        fma2(sacc[i * 4 + j], a0[j], b0[i]);
                        fma2(sacc[i * 4 + j], a1[j], b1[i]);
                    }
            }
#pragma unroll
            for (int i = 0; i < 4; i++)
#pragma unroll
                for (int j = 0; j < 4; j++) {
                    float2 v = up2(sacc[i * 4 + j]);
                    att_s[ch][tyy + 8 * i][txx + 8 * j] = v.x + v.y;
                }
        }
        __syncthreads();

        // ---- Phase S: softmax over channels, in place; mask from g_maskT ----
        {
            int ml = t >> 3;            // 0..31
            int nb = (t & 7) * 4;       // n group of 4
            float4 e[8];
            float4 sum = make_float4(0.f, 0.f, 0.f, 0.f);
#pragma unroll
            for (int k = 0; k < 8; k++) {
                float4 v = *(const float4*)&att_s[k][ml][nb];
                // |score| <= 1 (unit rows): softmax safe without max subtraction
                e[k].x = __expf(v.x); e[k].y = __expf(v.y);
                e[k].z = __expf(v.z); e[k].w = __expf(v.w);
                sum.x += e[k].x; sum.y += e[k].y; sum.z += e[k].z; sum.w += e[k].w;
            }
            unsigned wb = g_maskT[(size_t)(m0 + ml) * 64 + (n0 >> 5)] >> nb;
            float4 inv;
            inv.x = (wb & 1u)        ? __fdividef(1.f, sum.x) : 0.f;
            inv.y = ((wb >> 1) & 1u) ? __fdividef(1.f, sum.y) : 0.f;
            inv.z = ((wb >> 2) & 1u) ? __fdividef(1.f, sum.z) : 0.f;
            inv.w = ((wb >> 3) & 1u) ? __fdividef(1.f, sum.w) : 0.f;
#pragma unroll
            for (int k = 0; k < 8; k++) {
                float4 o;
                o.x = e[k].x * inv.x; o.y = e[k].y * inv.y;
                o.z = e[k].z * inv.z; o.w = e[k].w * inv.w;
                *(float4*)&att_s[k][ml][nb] = o;
            }
        }
        __syncthreads();

        // ---- Phase B: acc[n(pair),d] += att[kb][m][n] * Z[kb][m][d]  (f32x2) ----
#pragma unroll 4
        for (int m = 0; m < 32; m++) {
            ull z2 = bc2(Zm_s[m][kb * 32 + d]);
            const float4* arow = (const float4*)&att_s[kb][m][0];
#pragma unroll
            for (int q = 0; q < 8; q++) {
                float4 a = arow[q];              // broadcast LDS.128
                fma2(acc2[2 * q],     pk(a.x, a.y), z2);
                fma2(acc2[2 * q + 1], pk(a.z, a.w), z2);
            }
        }
    }

    float* dst = g_part[blockIdx.y];
#pragma unroll
    for (int q = 0; q < 16; q++) {
        float2 v = up2(acc2[q]);
        dst[(size_t)(n0 + 2 * q) * CDIM + kb * 32 + d]     = v.x;
        dst[(size_t)(n0 + 2 * q + 1) * CDIM + kb * 32 + d] = v.y;
    }
}

// ---------------- residual + sum partials + L2 norm ----------------
__global__ void norm_kernel(int zi, int zo, float* __restrict__ outp) {
    int n = blockIdx.x, t = threadIdx.x;
    size_t i = (size_t)n * CDIM + t;
    float v = g_Z[zi][i] + g_part[0][i] + g_part[1][i] + g_part[2][i] + g_part[3][i];
    float ss = v * v;
#pragma unroll
    for (int o = 16; o; o >>= 1) ss += __shfl_xor_sync(0xffffffffu, ss, o);
    float r = v / fmaxf(sqrtf(ss), 1e-12f);
    if (outp) outp[i] = r; else g_Z[zo][i] = r;
}

extern "C" void kernel_launch(void* const* d_in, const int* in_sizes, int n_in,
                              void* d_out, int out_size) {
    const int* adj = nullptr; const float* feat = nullptr;
    const float* W = nullptr; const float* b = nullptr;
    for (int i = 0; i < n_in; i++) {
        switch (in_sizes[i]) {
            case NN * NN:      adj  = (const int*)d_in[i];   break;
            case NN * 128:     feat = (const float*)d_in[i]; break;
            case 8 * 128 * 32: W    = (const float*)d_in[i]; break;
            case 256:          b    = (const float*)d_in[i]; break;
        }
    }
    float* out = (float*)d_out;

    const int SMEM = (2 * TN * ZS + KCH * TN * TMT) * 4;   // 99328 bytes
    cudaFuncSetAttribute(iter_kernel, cudaFuncAttributeMaxDynamicSharedMemorySize, SMEM);

    pack_maskT_kernel<<<dim3(64, 8), 256>>>(adj);
    proj_kernel<<<NN, 256>>>(feat, W, b);

    int cur = 0;
    for (int it = 0; it < 4; it++) {
        dim3 grid(NN / TN, MS);
        iter_kernel<<<grid, 256, SMEM>>>(cur);
        norm_kernel<<<NN, 256>>>(cur, cur ^ 1, (it == 3) ? out : nullptr);
        cur ^= 1;
    }
}